// round 15
// baseline (speedup 1.0000x reference)
#include <cuda_runtime.h>
#include <cuda_fp16.h>
#include <stdint.h>

// ---------------------------------------------------------------------------
// Channel attention, factorized; classic tensor cores mma.m16n8k16 fp16->f32.
//   P[b]  = q @ x[b]^T                   1-MMA fp16, split-K=2, 3-stage BK=64
//   E[b]  = kw . P[b] (split-K=2, f32 partials; +kb(x)qsum fused in smtrans)
//   att   = softmax rows(E)              fused: partial-sum + bias + transpose
//   W2[b] = attT . vwT                   1-MMA, 3-stage
//   out   = gamma*(W2 @ xT + b2) + x     1-MMA, 3-stage, f32 epilogue
// ---------------------------------------------------------------------------

#define BATCH 8
#define CCH   512
#define NPIX  4096

__device__ __half g_xh [BATCH*CCH*NPIX];
__device__ __half g_xTh[BATCH*CCH*NPIX];
__device__ __half g_qh [CCH*NPIX];
__device__ __half g_kwh[CCH*CCH];
__device__ __half g_kwl[CCH*CCH];
__device__ __half g_vwTh[CCH*CCH];
__device__ __half g_Ph [BATCH*CCH*CCH];
__device__ __half g_aTh[BATCH*CCH*CCH];
__device__ __half g_W2h[BATCH*CCH*CCH];
__device__ float g_Pp[2*BATCH*CCH*CCH];   // split-K partials (GEMM1, then GEMM2)
__device__ float g_qsum[CCH];
__device__ float g_bias2[BATCH*CCH];

// --------------------------- asm helpers -----------------------------------
__device__ __forceinline__ uint32_t smem_u32(const void* p) {
    uint32_t a;
    asm("{ .reg .u64 t; cvta.to.shared.u64 t, %1; cvt.u32.u64 %0, t; }" : "=r"(a) : "l"(p));
    return a;
}
__device__ __forceinline__ void cp16(uint32_t saddr, const void* g) {
    asm volatile("cp.async.cg.shared.global [%0], [%1], 16;" :: "r"(saddr), "l"(g) : "memory");
}
__device__ __forceinline__ void cp_commit() {
    asm volatile("cp.async.commit_group;" ::: "memory");
}
template<int N>
__device__ __forceinline__ void cp_wait() {
    asm volatile("cp.async.wait_group %0;" :: "n"(N) : "memory");
}
__device__ __forceinline__ void ldsm4(uint32_t* r, uint32_t a) {
    asm volatile("ldmatrix.sync.aligned.m8n8.x4.shared.b16 {%0,%1,%2,%3}, [%4];"
                 : "=r"(r[0]), "=r"(r[1]), "=r"(r[2]), "=r"(r[3]) : "r"(a));
}
__device__ __forceinline__ void mma16816(float* d, const uint32_t* a, const uint32_t* b) {
    asm volatile("mma.sync.aligned.m16n8k16.row.col.f32.f16.f16.f32 "
                 "{%0,%1,%2,%3}, {%4,%5,%6,%7}, {%8,%9}, {%0,%1,%2,%3};"
                 : "+f"(d[0]), "+f"(d[1]), "+f"(d[2]), "+f"(d[3])
                 : "r"(a[0]), "r"(a[1]), "r"(a[2]), "r"(a[3]), "r"(b[0]), "r"(b[1]));
}
__device__ __forceinline__ uint32_t pack2(__half a, __half b) {
    __half2 p; p.x = a; p.y = b;
    return *reinterpret_cast<uint32_t*>(&p);
}

// --------------------------- GEMM kernel -----------------------------------
// CTA tile 128x128, BK=64. STAGES=3 (NMMA=1): 1 barrier/chunk, wait<1> slack.
// STAGES=2 (NMMA=2): R14 double buffer. Row padded to 144B.
#define RSB   144
#define TILEB (128*RSB)     // 18432

// EPI: 1 = f32 + e1[m]*e2[n]; 2 = gamma*(v+e1)+xres; 3 = half out; 4 = f32 plain.
template<int NMMA, int EPI, bool KSPLIT, int STAGES>
__global__ __launch_bounds__(256)
void gemm_f16(const __half* __restrict__ Ah, const __half* __restrict__ Al,
              const __half* __restrict__ Bh,
              int ldA, int ldB, long sA, long sB, int K,
              __half* __restrict__ Dh,
              float* __restrict__ Dout, int ldD, long sD,
              const float* __restrict__ e1, long se1,
              const float* __restrict__ e2,
              const float* __restrict__ xres,
              const float* __restrict__ gptr)
{
    constexpr int NTILES = (NMMA == 2) ? 3 : 2;
    constexpr int STGB   = NTILES * TILEB;
    constexpr int BOFF   = (NMMA == 2) ? 2 * TILEB : TILEB;

    extern __shared__ char sm[];
    const uint32_t sb = smem_u32(sm);
    const int tid = threadIdx.x, lane = tid & 31, wid = tid >> 5;
    const int wm = (wid >> 2) * 64, wn = (wid & 3) * 32;
    const int b      = KSPLIT ? (blockIdx.z & 7) : blockIdx.z;
    const int kslice = KSPLIT ? (blockIdx.z >> 3) : 0;
    const int m0 = blockIdx.y * 128, n0 = blockIdx.x * 128;

    Ah += b * sA + (long)kslice * K;
    if (NMMA == 2) Al += (long)kslice * K;
    Bh += b * sB + (long)kslice * K;
    if (KSPLIT) Dout += (long)kslice * BATCH * sD;

    const uint32_t aoff = ((lane & 7) + 8 * ((lane >> 3) & 1)) * RSB + (lane >> 4) * 16;
    const uint32_t boff = ((lane & 7) + 8 * (lane >> 4)) * RSB + ((lane >> 3) & 1) * 16;

    float acc[4][4][4];
    #pragma unroll
    for (int i = 0; i < 4; i++)
        #pragma unroll
        for (int j = 0; j < 4; j++)
            #pragma unroll
            for (int v = 0; v < 4; v++) acc[i][j][v] = 0.f;

    const int nc = K >> 6;      // 64-wide chunks

    auto load_stage = [&](int stage, int k0) {
        uint32_t base = sb + stage * STGB;
        #pragma unroll
        for (int it = 0; it < 4; it++) {
            int idx = it * 256 + tid;
            int row = idx >> 3, c16 = idx & 7;
            uint32_t so = base + row * RSB + c16 * 16;
            long ga = (long)(m0 + row) * ldA + k0 + c16 * 8;
            cp16(so, Ah + ga);
            if (NMMA == 2) cp16(so + TILEB, Al + ga);
            cp16(so + BOFF, Bh + (long)(n0 + row) * ldB + k0 + c16 * 8);
        }
    };

    auto compute_stage = [&](int stage) {
        uint32_t Abase = sb + stage * STGB;
        uint32_t Bbase = Abase + BOFF;
        #pragma unroll
        for (int ks = 0; ks < 4; ks++) {
            uint32_t kb2 = ks * 32;
            uint32_t ah[4][4], al[4][4], bh[4][2];
            #pragma unroll
            for (int mi = 0; mi < 4; mi++) {
                ldsm4(ah[mi], Abase + (wm + mi * 16) * RSB + kb2 + aoff);
                if (NMMA == 2) ldsm4(al[mi], Abase + TILEB + (wm + mi * 16) * RSB + kb2 + aoff);
            }
            #pragma unroll
            for (int nb = 0; nb < 2; nb++) {
                uint32_t t[4];
                ldsm4(t, Bbase + (wn + nb * 16) * RSB + kb2 + boff);
                bh[2*nb][0] = t[0]; bh[2*nb][1] = t[1];
                bh[2*nb+1][0] = t[2]; bh[2*nb+1][1] = t[3];
            }
            #pragma unroll
            for (int mi = 0; mi < 4; mi++)
                #pragma unroll
                for (int ni = 0; ni < 4; ni++) {
                    mma16816(acc[mi][ni], ah[mi], bh[ni]);
                    if (NMMA == 2) mma16816(acc[mi][ni], al[mi], bh[ni]);
                }
        }
    };

    if (STAGES == 3) {
        load_stage(0, 0);
        cp_commit();
        if (nc > 1) { load_stage(1, 64); cp_commit(); }
        for (int c = 0; c < nc; c++) {
            if (c + 1 < nc) cp_wait<1>(); else cp_wait<0>();
            __syncthreads();
            if (c + 2 < nc) { load_stage((c + 2) % 3, (c + 2) * 64); cp_commit(); }
            compute_stage(c % 3);
        }
    } else {
        load_stage(0, 0);
        cp_commit();
        for (int c = 0; c < nc; c++) {
            cp_wait<0>();
            __syncthreads();
            if (c + 1 < nc) { load_stage((c + 1) & 1, (c + 1) * 64); cp_commit(); }
            compute_stage(c & 1);
            __syncthreads();
        }
    }

    // ------------------------------ epilogue -------------------------------
    float g = 0.f;
    if (EPI == 2) g = gptr[0];
    #pragma unroll
    for (int mi = 0; mi < 4; mi++) {
        #pragma unroll
        for (int half_ = 0; half_ < 2; half_++) {
            int r = m0 + wm + mi * 16 + (lane >> 2) + half_ * 8;
            float e1r = 0.f;
            if (EPI == 1) e1r = e1[r];
            if (EPI == 2) e1r = e1[b * se1 + r];
            #pragma unroll
            for (int ni = 0; ni < 4; ni++) {
                int cidx = n0 + wn + ni * 8 + 2 * (lane & 3);
                float v0 = acc[mi][ni][half_ * 2 + 0];
                float v1 = acc[mi][ni][half_ * 2 + 1];
                long idx = (long)r * ldD + cidx;
                if (EPI == 3) {
                    __half2 ph;
                    ph.x = __float2half_rn(v0); ph.y = __float2half_rn(v1);
                    *reinterpret_cast<__half2*>(Dh + b * sD + idx) = ph;
                } else if (EPI == 4) {
                    float2 o; o.x = v0; o.y = v1;
                    *reinterpret_cast<float2*>(Dout + b * sD + idx) = o;
                } else if (EPI == 1) {
                    float2 o;
                    o.x = v0 + e1r * e2[cidx];
                    o.y = v1 + e1r * e2[cidx + 1];
                    *reinterpret_cast<float2*>(Dout + b * sD + idx) = o;
                } else {
                    float2 xr = *reinterpret_cast<const float2*>(xres + b * sD + idx);
                    float2 o;
                    o.x = g * (v0 + e1r) + xr.x;
                    o.y = g * (v1 + e1r) + xr.y;
                    *reinterpret_cast<float2*>(Dout + b * sD + idx) = o;
                }
            }
        }
    }
}

// split-K reduction for GEMM1: Ph = half(p0 + p1)
__global__ __launch_bounds__(256)
void reduceP_kernel(const float4* __restrict__ p0, const float4* __restrict__ p1,
                    uint2* __restrict__ Ph)
{
    int i = blockIdx.x * 256 + threadIdx.x;
    float4 a = p0[i], c = p1[i];
    uint2 u;
    u.x = pack2(__float2half_rn(a.x + c.x), __float2half_rn(a.y + c.y));
    u.y = pack2(__float2half_rn(a.z + c.z), __float2half_rn(a.w + c.w));
    Ph[i] = u;
}

// ------------------------- prep kernels ------------------------------------
__global__ __launch_bounds__(256)
void xprep_kernel(const float* __restrict__ x,
                  __half* __restrict__ xh, __half* __restrict__ xTh)
{
    __shared__ __half t[64][66];
    const int b  = blockIdx.z;
    const int n0 = blockIdx.x * 64, c0 = blockIdx.y * 64;
    const int tx = threadIdx.x & 15, ty = threadIdx.x >> 4;
    const long sb_ = (long)b * CCH * NPIX;
    const float* xb = x + sb_;

    #pragma unroll
    for (int i = 0; i < 4; i++) {
        int cl = ty + 16 * i;
        float4 v = *reinterpret_cast<const float4*>(xb + (long)(c0 + cl) * NPIX + n0 + tx * 4);
        uint32_t p0 = pack2(__float2half_rn(v.x), __float2half_rn(v.y));
        uint32_t p1 = pack2(__float2half_rn(v.z), __float2half_rn(v.w));
        uint2 u; u.x = p0; u.y = p1;
        *reinterpret_cast<uint2*>(xh + sb_ + (long)(c0 + cl) * NPIX + n0 + tx * 4) = u;
        *reinterpret_cast<uint32_t*>(&t[cl][tx * 4])     = p0;
        *reinterpret_cast<uint32_t*>(&t[cl][tx * 4 + 2]) = p1;
    }
    __syncthreads();
    #pragma unroll
    for (int i = 0; i < 4; i++) {
        int nl = ty + 16 * i;
        uint2 u;
        u.x = pack2(t[tx*4+0][nl], t[tx*4+1][nl]);
        u.y = pack2(t[tx*4+2][nl], t[tx*4+3][nl]);
        *reinterpret_cast<uint2*>(xTh + sb_ + (long)(n0 + nl) * CCH + c0 + tx * 4) = u;
    }
}

__global__ __launch_bounds__(256)
void qprep_kernel(const float* __restrict__ q, __half* __restrict__ qh)
{
    const int d = blockIdx.x, tid = threadIdx.x;
    const float4* row = reinterpret_cast<const float4*>(q + (long)d * NPIX);
    uint2* orow = reinterpret_cast<uint2*>(qh + (long)d * NPIX);
    float s = 0.f;
    #pragma unroll
    for (int j = 0; j < 4; j++) {
        int i = tid + j * 256;
        float4 v = row[i];
        s += v.x + v.y + v.z + v.w;
        uint2 u;
        u.x = pack2(__float2half_rn(v.x), __float2half_rn(v.y));
        u.y = pack2(__float2half_rn(v.z), __float2half_rn(v.w));
        orow[i] = u;
    }
    #pragma unroll
    for (int o = 16; o; o >>= 1) s += __shfl_xor_sync(0xffffffffu, s, o);
    __shared__ float sh[8];
    if ((tid & 31) == 0) sh[tid >> 5] = s;
    __syncthreads();
    if (tid == 0) {
        float t = 0.f;
        #pragma unroll
        for (int i = 0; i < 8; i++) t += sh[i];
        g_qsum[d] = t;
    }
}

__global__ __launch_bounds__(256)
void wprep_kernel(const float* __restrict__ kw, const float* __restrict__ vw,
                  uint2* __restrict__ kwh, uint2* __restrict__ kwl,
                  __half* __restrict__ vwTh)
{
    __shared__ float smf[32][33];
    if (blockIdx.x < 256) {
        int i = blockIdx.x * 256 + threadIdx.x;
        float4 v = reinterpret_cast<const float4*>(kw)[i];
        float f[4] = {v.x, v.y, v.z, v.w};
        __half h[4], l[4];
        #pragma unroll
        for (int j = 0; j < 4; j++) {
            h[j] = __float2half_rn(f[j]);
            l[j] = __float2half_rn(f[j] - __half2float(h[j]));
        }
        uint2 uh, ul;
        uh.x = pack2(h[0], h[1]); uh.y = pack2(h[2], h[3]);
        ul.x = pack2(l[0], l[1]); ul.y = pack2(l[2], l[3]);
        kwh[i] = uh; kwl[i] = ul;
    } else {
        int t = blockIdx.x - 256;
        int x0 = (t & 15) * 32, y0 = (t >> 4) * 32;
        int tx = threadIdx.x & 31, ty = threadIdx.x >> 5;
        #pragma unroll
        for (int i = 0; i < 4; i++)
            smf[ty + i * 8][tx] = vw[(long)(y0 + ty + i * 8) * CCH + x0 + tx];
        __syncthreads();
        #pragma unroll
        for (int i = 0; i < 4; i++)
            vwTh[(long)(x0 + ty + i * 8) * CCH + y0 + tx] = __float2half_rn(smf[tx][ty + i * 8]);
    }
}

// fused: E-row = p0 + p1 + kb[c]*qsum[.]; softmax; transposed fp16 -> aTh
__global__ __launch_bounds__(256)
void smtrans_kernel(const float* __restrict__ p0, const float* __restrict__ p1,
                    const float* __restrict__ kb, __half* __restrict__ aTh)
{
    __shared__ __half s[8][512];
    const int w = threadIdx.x >> 5, lane = threadIdx.x & 31;
    const long r = (long)blockIdx.x * 8 + w;     // r = b*512 + c
    const int c = (int)(r & 511);
    const float kbc = kb[c];
    const float* r0 = p0 + r * CCH;
    const float* r1 = p1 + r * CCH;

    float v[16];
    float m = -1e30f;
    #pragma unroll
    for (int k = 0; k < 16; k++) {
        int d = lane + 32 * k;
        v[k] = r0[d] + r1[d] + kbc * g_qsum[d];
        m = fmaxf(m, v[k]);
    }
    #pragma unroll
    for (int o = 16; o; o >>= 1) m = fmaxf(m, __shfl_xor_sync(0xffffffffu, m, o));
    float ss = 0.f;
    #pragma unroll
    for (int k = 0; k < 16; k++) { v[k] = expf(v[k] - m); ss += v[k]; }
    #pragma unroll
    for (int o = 16; o; o >>= 1) ss += __shfl_xor_sync(0xffffffffu, ss, o);
    float inv = 1.f / ss;
    #pragma unroll
    for (int k = 0; k < 16; k++)
        s[w][lane + 32 * k] = __float2half_rn(v[k] * inv);
    __syncthreads();

    const int b  = (blockIdx.x * 8) >> 9;
    const int c0 = (blockIdx.x * 8) & 511;
    __half* out = aTh + (long)b * CCH * CCH + c0;
    #pragma unroll
    for (int dd = 0; dd < 2; dd++) {
        int d = 2 * threadIdx.x + dd;
        uint4 u;
        u.x = pack2(s[0][d], s[1][d]);
        u.y = pack2(s[2][d], s[3][d]);
        u.z = pack2(s[4][d], s[5][d]);
        u.w = pack2(s[6][d], s[7][d]);
        *reinterpret_cast<uint4*>(out + (long)d * CCH) = u;
    }
}

// bias2[b,c] = sum_d aTh[(b,c)][d]*vb[d]
__global__ __launch_bounds__(256)
void bias2_kernel(const __half* __restrict__ aTh, const float* __restrict__ vb)
{
    const int row = blockIdx.x * 8 + (threadIdx.x >> 5);
    const int lane = threadIdx.x & 31;
    const __half* ar = aTh + (long)row * CCH;
    float s = 0.f;
    #pragma unroll
    for (int k = 0; k < 16; k++) {
        int d = lane + 32 * k;
        s += __half2float(ar[d]) * vb[d];
    }
    #pragma unroll
    for (int o = 16; o; o >>= 1) s += __shfl_xor_sync(0xffffffffu, s, o);
    if (lane == 0) g_bias2[row] = s;
}

// ---------------------------------------------------------------------------
extern "C" void kernel_launch(void* const* d_in, const int* in_sizes, int n_in,
                              void* d_out, int out_size)
{
    const float* x     = (const float*)d_in[0];
    const float* q     = (const float*)d_in[1];
    const float* kw    = (const float*)d_in[2];
    const float* kb    = (const float*)d_in[3];
    const float* vw    = (const float*)d_in[4];
    const float* vb    = (const float*)d_in[5];
    const float* gamma = (const float*)d_in[6];
    float* out = (float*)d_out;

    const int SM3ST = 3 * 2 * TILEB;   // 110592 (NMMA=1, 3-stage)
    const int SM2ST = 2 * 3 * TILEB;   // 110592 (NMMA=2, 2-stage)
    cudaFuncSetAttribute((const void*)gemm_f16<1,4,true,3>,  cudaFuncAttributeMaxDynamicSharedMemorySize, SM3ST);
    cudaFuncSetAttribute((const void*)gemm_f16<1,2,false,3>, cudaFuncAttributeMaxDynamicSharedMemorySize, SM3ST);
    cudaFuncSetAttribute((const void*)gemm_f16<1,3,false,3>, cudaFuncAttributeMaxDynamicSharedMemorySize, SM3ST);
    cudaFuncSetAttribute((const void*)gemm_f16<2,4,true,2>,  cudaFuncAttributeMaxDynamicSharedMemorySize, SM2ST);

    __half *xh, *xTh, *qh, *kwh, *kwl, *vwTh, *Ph, *aTh, *W2h;
    float *pq, *pb2, *pPp;
    cudaGetSymbolAddress((void**)&xh,  g_xh);
    cudaGetSymbolAddress((void**)&xTh, g_xTh);
    cudaGetSymbolAddress((void**)&qh,  g_qh);
    cudaGetSymbolAddress((void**)&kwh, g_kwh);
    cudaGetSymbolAddress((void**)&kwl, g_kwl);
    cudaGetSymbolAddress((void**)&vwTh,g_vwTh);
    cudaGetSymbolAddress((void**)&Ph,  g_Ph);
    cudaGetSymbolAddress((void**)&aTh, g_aTh);
    cudaGetSymbolAddress((void**)&W2h, g_W2h);
    cudaGetSymbolAddress((void**)&pPp, g_Pp);
    cudaGetSymbolAddress((void**)&pq,  g_qsum);
    cudaGetSymbolAddress((void**)&pb2, g_bias2);

    const long sCC = (long)CCH * CCH;
    const long sCN = (long)CCH * NPIX;

    // ---- prep ----
    qprep_kernel<<<CCH, 256>>>(q, qh);
    xprep_kernel<<<dim3(NPIX/64, CCH/64, BATCH), 256>>>(x, xh, xTh);
    wprep_kernel<<<512, 256>>>(kw, vw, (uint2*)kwh, (uint2*)kwl, vwTh);

    // ---- GEMM1 (split-K=2, 3-stage): Pp[s][b][d][c] ----
    gemm_f16<1,4,true,3><<<dim3(4,4,16), 256, SM3ST>>>(
        qh, (const __half*)0, xh, NPIX, NPIX, 0, sCN, 2048,
        (__half*)0, pPp, CCH, sCC,
        (const float*)0, 0, (const float*)0, (const float*)0, (const float*)0);

    reduceP_kernel<<<(BATCH*CCH*CCH/4)/256, 256>>>(
        (const float4*)pPp, (const float4*)(pPp + BATCH*sCC), (uint2*)Ph);

    // ---- GEMM2 (split-K=2): E-partials into g_Pp (g_Pp free after reduceP) ----
    gemm_f16<2,4,true,2><<<dim3(4,4,16), 256, SM2ST>>>(
        kwh, kwl, Ph, CCH, CCH, 0, sCC, 256,
        (__half*)0, pPp, CCH, sCC,
        (const float*)0, 0, (const float*)0, (const float*)0, (const float*)0);

    // ---- fused partial-sum + kb(x)qsum + softmax + transpose, then bias2 ----
    smtrans_kernel<<<BATCH*CCH/8, 256>>>(pPp, pPp + BATCH*sCC, kb, aTh);
    bias2_kernel<<<BATCH*CCH/8, 256>>>(aTh, vb);

    // ---- GEMM3 (3-stage): W2[b][c][o] = sum_d attT[c][d]*vwT[o][d] ----
    gemm_f16<1,3,false,3><<<dim3(4,4,BATCH), 256, SM3ST>>>(
        aTh, (const __half*)0, vwTh, CCH, CCH, sCC, 0, CCH,
        W2h, (float*)0, CCH, sCC,
        (const float*)0, 0, (const float*)0, (const float*)0, (const float*)0);

    // ---- GEMM4 (3-stage): out = gamma*(W2 @ xT + bias2) + x ----
    gemm_f16<1,2,false,3><<<dim3(NPIX/128, 4, BATCH), 256, SM3ST>>>(
        W2h, (const __half*)0, xTh, CCH, CCH, sCC, sCN, CCH,
        (__half*)0, out, NPIX, sCN,
        pb2, CCH, (const float*)0, x, gamma);
}